// round 1
// baseline (speedup 1.0000x reference)
#include <cuda_runtime.h>

#define NN 100000
#define EE 1600000
#define GG 1000
#define BN_EPS 1e-5f

// ---------------- device scratch (no allocations allowed) ----------------
__device__ int   g_deg[NN];
__device__ int   g_off[NN + 1];
__device__ int   g_fill[NN];
__device__ int   g_bsum[128];
__device__ int   g_srcs[EE];
__device__ float g_dinv[NN];
__device__ float g_gbuf[(size_t)NN * 64];      // per-layer (h@W)*dinv
__device__ float g_concat[(size_t)NN * 256];   // JK concat buffer
__device__ float g_pooled[GG * 256];
__device__ int   g_gstart[GG + 1];

// ---------------- graph prep ----------------
__global__ void k_zero(int n) {
    int i = blockIdx.x * blockDim.x + threadIdx.x;
    if (i < n) { g_deg[i] = 0; g_fill[i] = 0; }
}

__global__ void k_hist(const int* __restrict__ dst, int e) {
    int i = blockIdx.x * blockDim.x + threadIdx.x;
    if (i < e) atomicAdd(&g_deg[dst[i]], 1);
}

__global__ void k_scanA(int n) {
    __shared__ int sm[1024];
    int i = blockIdx.x * 1024 + threadIdx.x;
    int v = (i < n) ? g_deg[i] : 0;
    sm[threadIdx.x] = v;
    __syncthreads();
    #pragma unroll
    for (int o = 1; o < 1024; o <<= 1) {
        int t = (threadIdx.x >= o) ? sm[threadIdx.x - o] : 0;
        __syncthreads();
        sm[threadIdx.x] += t;
        __syncthreads();
    }
    if (i < n) g_off[i] = sm[threadIdx.x] - v;     // exclusive within block
    if (threadIdx.x == 1023) g_bsum[blockIdx.x] = sm[1023];
}

__global__ void k_scanB(int nb, int e, int n) {
    if (threadIdx.x == 0) {
        int acc = 0;
        for (int b = 0; b < nb; b++) { int t = g_bsum[b]; g_bsum[b] = acc; acc += t; }
        g_off[n] = e;
    }
}

__global__ void k_scanC(int n) {
    int i = blockIdx.x * 1024 + threadIdx.x;
    if (i < n) {
        g_off[i] += g_bsum[blockIdx.x];
        g_dinv[i] = rsqrtf((float)g_deg[i] + 1.0f);
    }
}

__global__ void k_scatter(const int* __restrict__ src, const int* __restrict__ dst, int e) {
    int i = blockIdx.x * blockDim.x + threadIdx.x;
    if (i < e) {
        int d = dst[i];
        int p = g_off[d] + atomicAdd(&g_fill[d], 1);
        g_srcs[p] = src[i];
    }
}

__global__ void k_gstart(const int* __restrict__ batch, int n, int gg) {
    int v = blockIdx.x * blockDim.x + threadIdx.x;
    if (v >= n) return;
    int b = batch[v];
    int prev = (v == 0) ? -1 : batch[v - 1];
    for (int q = prev + 1; q <= b; q++) g_gstart[q] = v;
    if (v == n - 1) for (int q = b + 1; q <= gg; q++) g_gstart[q] = n;
}

// ---------------- per-layer GEMM: g[v] = (h[v] @ W) * dinv[v] ----------------
__global__ __launch_bounds__(128) void k_gemm(const float* __restrict__ x, int layer,
                                              const float* __restrict__ W, int n) {
    __shared__ float ws[4096];          // 64x64 W
    __shared__ float ht[128 * 17];      // 128 rows x 16 k-cols, pad 17 (conflict-free)
    const float* h;
    int stride;
    if (layer == 0) { h = x; stride = 64; }
    else            { h = g_concat + (layer - 1) * 64; stride = 256; }

    int tid = threadIdx.x;
    int row0 = blockIdx.x * 128;

    // stage W (vectorized, coalesced)
    for (int idx = tid; idx < 1024; idx += 128)
        ((float4*)ws)[idx] = ((const float4*)W)[idx];

    float acc[64];
    #pragma unroll
    for (int j = 0; j < 64; j++) acc[j] = 0.0f;

    for (int kc = 0; kc < 4; kc++) {
        __syncthreads();
        // stage 128x16 h chunk, float4 coalesced
        #pragma unroll
        for (int it = 0; it < 4; it++) {
            int idx = tid + it * 128;      // 0..511
            int rr = idx >> 2, c4 = idx & 3;
            int row = row0 + rr;
            float4 v = make_float4(0.f, 0.f, 0.f, 0.f);
            if (row < n) v = *(const float4*)&h[(size_t)row * stride + kc * 16 + c4 * 4];
            ht[rr * 17 + c4 * 4 + 0] = v.x;
            ht[rr * 17 + c4 * 4 + 1] = v.y;
            ht[rr * 17 + c4 * 4 + 2] = v.z;
            ht[rr * 17 + c4 * 4 + 3] = v.w;
        }
        __syncthreads();
        #pragma unroll 4
        for (int k = 0; k < 16; k++) {
            float hk = ht[tid * 17 + k];
            const float4* wr = (const float4*)&ws[(kc * 16 + k) * 64];
            #pragma unroll
            for (int q = 0; q < 16; q++) {
                float4 wv = wr[q];           // broadcast LDS.128 across warp
                acc[4 * q + 0] += hk * wv.x;
                acc[4 * q + 1] += hk * wv.y;
                acc[4 * q + 2] += hk * wv.z;
                acc[4 * q + 3] += hk * wv.w;
            }
        }
    }

    int row = row0 + tid;
    if (row >= n) return;
    float di = g_dinv[row];
    float4* outp = (float4*)&g_gbuf[(size_t)row * 64];
    #pragma unroll
    for (int q = 0; q < 16; q++) {
        float4 o;
        o.x = acc[4 * q + 0] * di;
        o.y = acc[4 * q + 1] * di;
        o.z = acc[4 * q + 2] * di;
        o.w = acc[4 * q + 3] * di;
        outp[q] = o;
    }
}

// ---------------- propagation + bias + BN(eval) + ReLU, write concat slice ----------------
__global__ __launch_bounds__(256) void k_prop(int layer,
        const float* __restrict__ bias, const float* __restrict__ gamma,
        const float* __restrict__ beta, const float* __restrict__ mean,
        const float* __restrict__ var, int n)
{
    int w = (blockIdx.x * 256 + threadIdx.x) >> 5;
    int lane = threadIdx.x & 31;
    if (w >= n) return;

    const float2* gp = (const float2*)g_gbuf;   // row = 32 float2
    float2 acc = gp[(size_t)w * 32 + lane];     // self-loop term (g[v])

    int s0 = g_off[w], s1 = g_off[w + 1];
    int base = s0;
    int rem = s1 - s0;
    while (rem >= 32) {
        int s = g_srcs[base + lane];
        #pragma unroll
        for (int j = 0; j < 32; j++) {
            int sj = __shfl_sync(0xffffffffu, s, j);
            float2 v = gp[(size_t)sj * 32 + lane];
            acc.x += v.x; acc.y += v.y;
        }
        base += 32; rem -= 32;
    }
    if (rem > 0) {
        int s = g_srcs[base + ((lane < rem) ? lane : 0)];
        for (int j = 0; j < rem; j++) {
            int sj = __shfl_sync(0xffffffffu, s, j);
            float2 v = gp[(size_t)sj * 32 + lane];
            acc.x += v.x; acc.y += v.y;
        }
    }

    float di = g_dinv[w];
    int j0 = 2 * lane, j1 = j0 + 1;
    float o0 = di * acc.x + bias[j0];
    float o1 = di * acc.y + bias[j1];
    float sc0 = gamma[j0] * rsqrtf(var[j0] + BN_EPS);
    float sc1 = gamma[j1] * rsqrtf(var[j1] + BN_EPS);
    o0 = (o0 - mean[j0]) * sc0 + beta[j0];
    o1 = (o1 - mean[j1]) * sc1 + beta[j1];
    o0 = fmaxf(o0, 0.0f);
    o1 = fmaxf(o1, 0.0f);
    *(float2*)&g_concat[(size_t)w * 256 + layer * 64 + j0] = make_float2(o0, o1);
}

// ---------------- pooling: segmented sum over sorted batch ----------------
__global__ __launch_bounds__(256) void k_pool() {
    int g = blockIdx.x;
    int t = threadIdx.x;
    int s = g_gstart[g], e = g_gstart[g + 1];
    float acc = 0.0f;
    for (int v = s; v < e; v++) acc += g_concat[(size_t)v * 256 + t];
    g_pooled[g * 256 + t] = acc;
}

// ---------------- final MLP: relu(p@W1+b1)@W2+b2 ----------------
__global__ __launch_bounds__(64) void k_mlp(const float* __restrict__ W1, const float* __restrict__ b1,
                                            const float* __restrict__ W2, const float* __restrict__ b2,
                                            float* __restrict__ out) {
    __shared__ float p[256];
    __shared__ float hid[64];
    int g = blockIdx.x, t = threadIdx.x;
    for (int i = t; i < 256; i += 64) p[i] = g_pooled[g * 256 + i];
    __syncthreads();
    float acc = b1[t];
    #pragma unroll 8
    for (int k = 0; k < 256; k++) acc += p[k] * W1[k * 64 + t];
    hid[t] = fmaxf(acc, 0.0f);
    __syncthreads();
    if (t < 10) {
        float o = b2[t];
        #pragma unroll
        for (int j = 0; j < 64; j++) o += hid[j] * W2[j * 10 + t];
        out[g * 10 + t] = o;
    }
}

// ---------------- launch ----------------
extern "C" void kernel_launch(void* const* d_in, const int* in_sizes, int n_in,
                              void* d_out, int out_size) {
    int n = in_sizes[0] / 64;  if (n > NN) n = NN;
    int e = in_sizes[1] / 2;   if (e > EE) e = EE;
    int gg = out_size / 10;    if (gg > GG) gg = GG;

    // defensive: num_graphs scalar may or may not be materialized as input[3]
    int base = (n_in >= 4 && in_sizes[3] == 1) ? 4 : 3;

    const float* x     = (const float*)d_in[0];
    const int*   ei    = (const int*)  d_in[1];
    const int*   batch = (const int*)  d_in[2];
    const float* Ws[4] = { (const float*)d_in[base + 0], (const float*)d_in[base + 2],
                           (const float*)d_in[base + 4], (const float*)d_in[base + 6] };
    const float* bs[4] = { (const float*)d_in[base + 1], (const float*)d_in[base + 3],
                           (const float*)d_in[base + 5], (const float*)d_in[base + 7] };
    const float* bng = (const float*)d_in[base + 8];
    const float* bnb = (const float*)d_in[base + 9];
    const float* bnm = (const float*)d_in[base + 10];
    const float* bnv = (const float*)d_in[base + 11];
    const float* l1W = (const float*)d_in[base + 12];
    const float* l1b = (const float*)d_in[base + 13];
    const float* l2W = (const float*)d_in[base + 14];
    const float* l2b = (const float*)d_in[base + 15];
    float* out = (float*)d_out;

    const int* src = ei;
    const int* dst = ei + e;

    int nb = (n + 1023) / 1024;

    k_zero<<<(n + 255) / 256, 256>>>(n);
    k_hist<<<(e + 255) / 256, 256>>>(dst, e);
    k_scanA<<<nb, 1024>>>(n);
    k_scanB<<<1, 32>>>(nb, e, n);
    k_scanC<<<nb, 1024>>>(n);
    k_scatter<<<(e + 255) / 256, 256>>>(src, dst, e);
    k_gstart<<<(n + 255) / 256, 256>>>(batch, n, gg);

    int gemm_grid = (n + 127) / 128;
    int prop_grid = (n * 32 + 255) / 256;
    for (int i = 0; i < 4; i++) {
        k_gemm<<<gemm_grid, 128>>>(x, i, Ws[i], n);
        k_prop<<<prop_grid, 256>>>(i, bs[i], bng + i * 64, bnb + i * 64,
                                   bnm + i * 64, bnv + i * 64, n);
    }

    k_pool<<<gg, 256>>>();
    k_mlp<<<gg, 64>>>(l1W, l1b, l2W, l2b, out);
}